// round 1
// baseline (speedup 1.0000x reference)
#include <cuda_runtime.h>
#include <math.h>

#define B_   4
#define N_   2048
#define KD_  129      // D_IN + 1
#define H_   8
#define DO_  64
#define AD_  65       // D_OUT + 1 (ambient)
#define EPS_ 1e-7f

// ---------------- scratch (device globals; no allocations allowed) ----------
// Q, K stored d-major: [b*H+h][a(65)][n(2048)]  (Q time row negated)
// V, Mu stored n-major: [b*H+h][n(2048)][a(65)]
__device__ float g_Q [B_*H_*AD_*N_];
__device__ float g_K [B_*H_*AD_*N_];
__device__ float g_V [B_*H_*N_*AD_];
__device__ float g_Mu[B_*H_*N_*AD_];

// ---------------- projection: s = x @ W + b, lift to hyperboloid ------------
// grid (32 n-tiles, 24 = h + 8*m, B), block 256 (16x16 -> 4x4 microtiles)
#define PROJ_SMEM ((64*130 + 129*64) * 4)

__global__ __launch_bounds__(256) void proj_kernel(
    const float* __restrict__ x,
    const float* __restrict__ Wq, const float* __restrict__ Wk,
    const float* __restrict__ Wv,
    const float* __restrict__ bq, const float* __restrict__ bk,
    const float* __restrict__ bv)
{
    extern __shared__ float sm[];
    float* xs = sm;                 // [64][130] x tile (padded)
    float* Ws = sm + 64*130;        // [129][64] weight tile
    float* Ts = sm;                 // overlay xs after GEMM: [64 d][65 pad] staging
    __shared__ float st_time[64];

    const int n0 = blockIdx.x * 64;
    const int h  = blockIdx.y & 7;
    const int m  = blockIdx.y >> 3;          // 0=Q 1=K 2=V
    const int b  = blockIdx.z;
    const float* W    = (m == 0 ? Wq : (m == 1 ? Wk : Wv)) + h * KD_ * DO_;
    const float* bias = (m == 0 ? bq : (m == 1 ? bk : bv)) + h * DO_;

    const int tid = threadIdx.x;
    const int tx = tid & 15, ty = tid >> 4;

    for (int idx = tid; idx < 64 * KD_; idx += 256) {
        int r = idx / KD_, kk = idx - r * KD_;
        xs[r * 130 + kk] = x[((size_t)b * N_ + n0 + r) * KD_ + kk];
    }
    for (int idx = tid; idx < KD_ * DO_; idx += 256)
        Ws[idx] = W[idx];                    // Ws[kk*64+d]
    __syncthreads();

    float acc[4][4];
    #pragma unroll
    for (int i = 0; i < 4; i++)
        #pragma unroll
        for (int j = 0; j < 4; j++)
            acc[i][j] = bias[tx * 4 + j];

    for (int kk = 0; kk < KD_; kk++) {
        float4 wv = *(const float4*)(Ws + kk * 64 + tx * 4);
        #pragma unroll
        for (int i = 0; i < 4; i++) {
            float a = xs[(ty * 4 + i) * 130 + kk];
            acc[i][0] += a * wv.x; acc[i][1] += a * wv.y;
            acc[i][2] += a * wv.z; acc[i][3] += a * wv.w;
        }
    }

    // per-row sum of squares across d (16 lanes of same ty hold all 64 cols)
    float rs[4];
    #pragma unroll
    for (int i = 0; i < 4; i++) {
        float s = acc[i][0]*acc[i][0] + acc[i][1]*acc[i][1]
                + acc[i][2]*acc[i][2] + acc[i][3]*acc[i][3];
        #pragma unroll
        for (int o = 1; o < 16; o <<= 1)
            s += __shfl_xor_sync(0xffffffffu, s, o);
        rs[i] = s;
    }
    __syncthreads();  // xs dead; safe to overlay Ts

    #pragma unroll
    for (int i = 0; i < 4; i++)
        #pragma unroll
        for (int j = 0; j < 4; j++)
            Ts[(tx * 4 + j) * 65 + ty * 4 + i] = acc[i][j];
    if (tx == 0)
        #pragma unroll
        for (int i = 0; i < 4; i++)
            st_time[ty * 4 + i] = sqrtf(1.0f + rs[i]);   // C_ATTN = 1
    __syncthreads();

    if (m < 2) {   // Q / K : d-major, row 0 = time (negated for Q)
        float* g = (m == 0 ? g_Q : g_K) + (size_t)(b * H_ + h) * AD_ * N_;
        float sgn = (m == 0) ? -1.0f : 1.0f;
        for (int idx = tid; idx < 64 * 64; idx += 256) {
            int d = idx >> 6, n = idx & 63;
            g[(size_t)(d + 1) * N_ + n0 + n] = Ts[d * 65 + n];
        }
        for (int n = tid; n < 64; n += 256)
            g[n0 + n] = sgn * st_time[n];
    } else {       // V : n-major [n][65], col 0 = time
        float* g = g_V + (size_t)(b * H_ + h) * N_ * AD_;
        for (int idx = tid; idx < 64 * AD_; idx += 256) {
            int n = idx / AD_, c = idx - n * AD_;
            g[(size_t)(n0 + n) * AD_ + c] = (c == 0) ? st_time[n]
                                                     : Ts[(c - 1) * 65 + n];
        }
    }
}

// ---------------- fused attention (flash-style, one-pass sum-exp) -----------
// grid (32 q-tiles, 32 bh), 256 threads.  BM=BN=64, d=65.
#define ATTN_SMEM ((65*64 + 65*64 + 64*68) * 4)   // Qs + (Ks|Ps union) + Vs

__global__ __launch_bounds__(256, 3) void attn_kernel(
    const float* __restrict__ scale_p)
{
    extern __shared__ float sm[];
    float* Qs   = sm;            // [65 d][64 n]
    float* KsPs = sm + 65 * 64;  // Ks [65][64]  aliased with  Ps [64][65]
    float* Vs   = sm + 2 * 65 * 64; // [64 j][68 pad] cols 0..64

    const int bh = blockIdx.y;
    const int n0 = blockIdx.x * 64;
    const float* Qg = g_Q + (size_t)bh * AD_ * N_;
    const float* Kg = g_K + (size_t)bh * AD_ * N_;
    const float* Vg = g_V + (size_t)bh * N_ * AD_;
    float*      Mug = g_Mu + (size_t)bh * N_ * AD_;

    const float alpha = 2.0f / (scale_p[0] + EPS_);
    const int tid = threadIdx.x;
    const int tx = tid & 15, ty = tid >> 4;

    for (int idx = tid; idx < AD_ * 64; idx += 256)
        Qs[idx] = Qg[(size_t)(idx >> 6) * N_ + n0 + (idx & 63)];

    float accv[4][5];
    float l[4] = {0.f, 0.f, 0.f, 0.f};
    #pragma unroll
    for (int i = 0; i < 4; i++)
        #pragma unroll
        for (int c = 0; c < 5; c++) accv[i][c] = 0.f;

    for (int kt = 0; kt < N_ / 64; kt++) {
        const int k0 = kt * 64;
        __syncthreads();   // prior PV done (and Qs ready on first iter)
        for (int idx = tid; idx < AD_ * 64; idx += 256)
            KsPs[idx] = Kg[(size_t)(idx >> 6) * N_ + k0 + (idx & 63)];
        for (int idx = tid; idx < 64 * AD_; idx += 256) {
            int j = idx / AD_, c = idx - j * AD_;
            Vs[j * 68 + c] = Vg[(size_t)(k0 + j) * AD_ + c];
        }
        __syncthreads();

        // S = Q~ K^T  (Lorentz inner product: time row pre-negated in Q)
        float s[4][4];
        #pragma unroll
        for (int i = 0; i < 4; i++)
            #pragma unroll
            for (int j = 0; j < 4; j++) s[i][j] = 0.f;

        for (int d = 0; d < AD_; d++) {
            float4 qv = *(const float4*)(Qs   + d * 64 + ty * 4);
            float4 kv = *(const float4*)(KsPs + d * 64 + tx * 4);
            s[0][0] += qv.x*kv.x; s[0][1] += qv.x*kv.y; s[0][2] += qv.x*kv.z; s[0][3] += qv.x*kv.w;
            s[1][0] += qv.y*kv.x; s[1][1] += qv.y*kv.y; s[1][2] += qv.y*kv.z; s[1][3] += qv.y*kv.w;
            s[2][0] += qv.z*kv.x; s[2][1] += qv.z*kv.y; s[2][2] += qv.z*kv.z; s[2][3] += qv.z*kv.w;
            s[3][0] += qv.w*kv.x; s[3][1] += qv.w*kv.y; s[3][2] += qv.w*kv.z; s[3][3] += qv.w*kv.w;
        }
        __syncthreads();   // everyone done reading Ks before Ps writes

        // P = exp(alpha*S); per-row constants of the score cancel in softmax.
        #pragma unroll
        for (int i = 0; i < 4; i++) {
            float rsum = 0.f;
            #pragma unroll
            for (int j = 0; j < 4; j++) {
                float p = __expf(alpha * s[i][j]);
                s[i][j] = p; rsum += p;
                KsPs[(ty * 4 + i) * 65 + tx * 4 + j] = p;   // Ps
            }
            #pragma unroll
            for (int o = 1; o < 16; o <<= 1)
                rsum += __shfl_xor_sync(0xffffffffu, rsum, o);
            l[i] += rsum;
        }
        __syncthreads();   // Ps visible

        // PV: acc[i][c] += P[i][j] * V[j][c]   (col 64 identical across tx)
        for (int j = 0; j < 64; j++) {
            float4 vv = *(const float4*)(Vs + j * 68 + tx * 4);
            float  ve = Vs[j * 68 + 64];
            #pragma unroll
            for (int i = 0; i < 4; i++) {
                float p = KsPs[(ty * 4 + i) * 65 + j];
                accv[i][0] += p * vv.x; accv[i][1] += p * vv.y;
                accv[i][2] += p * vv.z; accv[i][3] += p * vv.w;
                accv[i][4] += p * ve;
            }
        }
    }

    #pragma unroll
    for (int i = 0; i < 4; i++) {
        float inv = 1.0f / l[i];
        float* o = Mug + (size_t)(n0 + ty * 4 + i) * AD_;
        o[tx * 4 + 0] = accv[i][0] * inv;
        o[tx * 4 + 1] = accv[i][1] * inv;
        o[tx * 4 + 2] = accv[i][2] * inv;
        o[tx * 4 + 3] = accv[i][3] * inv;
        if (tx == 0) o[64] = accv[i][4] * inv;
    }
}

// ---------------- finalize: per-head normalize, head-mean, normalize, lift --
// one warp per (b,n); lanes cover a = lane, lane+32, (lane0: 64)
__global__ __launch_bounds__(256) void finalize_kernel(float* __restrict__ out)
{
    const int gw = (blockIdx.x * blockDim.x + threadIdx.x) >> 5;
    const int lane = threadIdx.x & 31;
    if (gw >= B_ * N_) return;
    const int b = gw >> 11, n = gw & (N_ - 1);

    float a0 = 0.f, a1 = 0.f, a2 = 0.f;
    for (int h = 0; h < H_; h++) {
        const float* mu = g_Mu + ((size_t)(b * H_ + h) * N_ + n) * AD_;
        float m0 = mu[lane];
        float m1 = mu[lane + 32];
        float m2 = (lane == 0) ? mu[64] : 0.f;
        float ss = m0 * m0 + m1 * m1 + m2 * m2;
        #pragma unroll
        for (int o = 16; o; o >>= 1) ss += __shfl_xor_sync(0xffffffffu, ss, o);
        float mu0 = __shfl_sync(0xffffffffu, m0, 0);
        float neg = 2.0f * mu0 * mu0 - ss;      // -<mu,mu>_L
        float inv = rsqrtf(fmaxf(neg, EPS_)) * (1.0f / H_);
        a0 += m0 * inv; a1 += m1 * inv; a2 += m2 * inv;
    }
    float ss = a0 * a0 + a1 * a1 + a2 * a2;
    #pragma unroll
    for (int o = 16; o; o >>= 1) ss += __shfl_xor_sync(0xffffffffu, ss, o);
    float av0 = __shfl_sync(0xffffffffu, a0, 0);
    float neg = 2.0f * av0 * av0 - ss;
    float inv2 = rsqrtf(fmaxf(neg, EPS_));
    float sp0 = a0 * inv2, sp1 = a1 * inv2, sp2 = a2 * inv2;

    // re-lift: time = sqrt(1/C_OUT + ||spatial||^2); spatial rescale = 1
    float ssp = sp1 * sp1 + ((lane == 0) ? sp2 * sp2 : sp0 * sp0);
    #pragma unroll
    for (int o = 16; o; o >>= 1) ssp += __shfl_xor_sync(0xffffffffu, ssp, o);
    float t = sqrtf(1.0f + ssp);

    float* o_ = out + ((size_t)b * N_ + n) * AD_;
    o_[lane]      = (lane == 0) ? t : sp0;
    o_[lane + 32] = sp1;
    if (lane == 0) o_[64] = sp2;
}

// ---------------- launch ----------------------------------------------------
extern "C" void kernel_launch(void* const* d_in, const int* in_sizes, int n_in,
                              void* d_out, int out_size)
{
    const float* x     = (const float*)d_in[0];
    const float* Wq    = (const float*)d_in[1];
    const float* Wk    = (const float*)d_in[2];
    const float* Wv    = (const float*)d_in[3];
    const float* bq    = (const float*)d_in[4];
    const float* bk    = (const float*)d_in[5];
    const float* bv    = (const float*)d_in[6];
    const float* scale = (const float*)d_in[7];
    float* out = (float*)d_out;

    cudaFuncSetAttribute(proj_kernel, cudaFuncAttributeMaxDynamicSharedMemorySize, PROJ_SMEM);
    cudaFuncSetAttribute(attn_kernel, cudaFuncAttributeMaxDynamicSharedMemorySize, ATTN_SMEM);

    proj_kernel<<<dim3(N_/64, 3*H_, B_), 256, PROJ_SMEM>>>(x, Wq, Wk, Wv, bq, bk, bv);
    attn_kernel<<<dim3(N_/64, B_*H_), 256, ATTN_SMEM>>>(scale);
    finalize_kernel<<<(B_*N_*32 + 255)/256, 256>>>(out);
}

// round 3
// speedup vs baseline: 4.5185x; 4.5185x over previous
#include <cuda_runtime.h>
#include <cuda_bf16.h>
#include <math.h>
#include <stdint.h>

#define B_   4
#define N_   2048
#define KD_  129
#define H_   8
#define DO_  64
#define AD_  65
#define BH_  (B_*H_)
#define EPS_ 1e-7f
#define MUP_ 68

// ---------------- scratch ----------------------------------------------------
// Q/K spatial: bf16 n-major [bh][n][64]. time fp32 separate.
// V^T: bf16 d-major [bh][72][N] (row0=time, 1..64 spatial, 65..71 zero)
__device__ __nv_bfloat16 g_Qb[BH_*N_*64];
__device__ __nv_bfloat16 g_Kb[BH_*N_*64];
__device__ float         g_Q0[BH_*N_];
__device__ float         g_K0[BH_*N_];
__device__ __nv_bfloat16 g_Vt[BH_*72*N_];
__device__ float         g_Mu[BH_*N_*MUP_];

// ---------------- helpers ----------------------------------------------------
__device__ __forceinline__ uint32_t smem_u32(const void* p) {
    uint32_t a;
    asm("{ .reg .u64 t; cvta.to.shared.u64 t, %1; cvt.u32.u64 %0, t; }" : "=r"(a) : "l"(p));
    return a;
}
__device__ __forceinline__ void cpa16(uint32_t dst, const void* src) {
    asm volatile("cp.async.cg.shared.global [%0], [%1], 16;" :: "r"(dst), "l"(src));
}
#define CP_COMMIT() asm volatile("cp.async.commit_group;" ::: "memory")
#define CP_WAIT1()  asm volatile("cp.async.wait_group 1;" ::: "memory")
#define CP_WAIT0()  asm volatile("cp.async.wait_group 0;" ::: "memory")

__device__ __forceinline__ void mma16816(float* d,
    uint32_t a0, uint32_t a1, uint32_t a2, uint32_t a3,
    uint32_t b0, uint32_t b1)
{
    asm volatile("mma.sync.aligned.m16n8k16.row.col.f32.bf16.bf16.f32 "
        "{%0,%1,%2,%3}, {%4,%5,%6,%7}, {%8,%9}, {%0,%1,%2,%3};"
        : "+f"(d[0]), "+f"(d[1]), "+f"(d[2]), "+f"(d[3])
        : "r"(a0), "r"(a1), "r"(a2), "r"(a3), "r"(b0), "r"(b1));
}
__device__ __forceinline__ float ex2f(float x) {
    float r; asm("ex2.approx.ftz.f32 %0, %1;" : "=f"(r) : "f"(x)); return r;
}
__device__ __forceinline__ uint32_t bf2(float lo, float hi) {
    uint32_t r; asm("cvt.rn.bf16x2.f32 %0, %1, %2;" : "=r"(r) : "f"(hi), "f"(lo)); return r;
}

// ---------------- projection -------------------------------------------------
#define PROJ_SMEM ((64*130 + 129*64) * 4)

__global__ __launch_bounds__(256) void proj_kernel(
    const float* __restrict__ x,
    const float* __restrict__ Wq, const float* __restrict__ Wk,
    const float* __restrict__ Wv,
    const float* __restrict__ bq, const float* __restrict__ bk,
    const float* __restrict__ bv)
{
    extern __shared__ float sm[];
    float* xs = sm;              // [64][130]
    float* Ws = sm + 64*130;     // [129][64]
    float* Ts = sm;              // overlay (V only)
    __shared__ float st_time[64];

    const int n0 = blockIdx.x * 64;
    const int h  = blockIdx.y & 7;
    const int m  = blockIdx.y >> 3;
    const int b  = blockIdx.z;
    const int bh = b * H_ + h;
    const float* W    = (m == 0 ? Wq : (m == 1 ? Wk : Wv)) + h * KD_ * DO_;
    const float* bias = (m == 0 ? bq : (m == 1 ? bk : bv)) + h * DO_;

    const int tid = threadIdx.x;
    const int tx = tid & 15, ty = tid >> 4;

    for (int idx = tid; idx < 64 * KD_; idx += 256) {
        int r = idx / KD_, kk = idx - r * KD_;
        xs[r * 130 + kk] = x[((size_t)b * N_ + n0 + r) * KD_ + kk];
    }
    for (int idx = tid; idx < KD_ * DO_; idx += 256)
        Ws[idx] = W[idx];
    __syncthreads();

    float acc[4][4];
    #pragma unroll
    for (int i = 0; i < 4; i++)
        #pragma unroll
        for (int j = 0; j < 4; j++)
            acc[i][j] = bias[tx * 4 + j];

    for (int kk = 0; kk < KD_; kk++) {
        float4 wv = *(const float4*)(Ws + kk * 64 + tx * 4);
        #pragma unroll
        for (int i = 0; i < 4; i++) {
            float a = xs[(ty * 4 + i) * 130 + kk];
            acc[i][0] += a * wv.x; acc[i][1] += a * wv.y;
            acc[i][2] += a * wv.z; acc[i][3] += a * wv.w;
        }
    }

    float rs[4];
    #pragma unroll
    for (int i = 0; i < 4; i++) {
        float s = acc[i][0]*acc[i][0] + acc[i][1]*acc[i][1]
                + acc[i][2]*acc[i][2] + acc[i][3]*acc[i][3];
        #pragma unroll
        for (int o = 1; o < 16; o <<= 1)
            s += __shfl_xor_sync(0xffffffffu, s, o);
        rs[i] = s;
    }

    if (m < 2) {
        __nv_bfloat16* gb = (m == 0 ? g_Qb : g_Kb) + (size_t)bh * N_ * 64;
        float*         g0 = (m == 0 ? g_Q0 : g_K0) + (size_t)bh * N_;
        #pragma unroll
        for (int i = 0; i < 4; i++) {
            int n = n0 + ty * 4 + i;
            __nv_bfloat162* p = (__nv_bfloat162*)(gb + (size_t)n * 64 + tx * 4);
            __nv_bfloat162 v0, v1;
            v0.x = __float2bfloat16_rn(acc[i][0]); v0.y = __float2bfloat16_rn(acc[i][1]);
            v1.x = __float2bfloat16_rn(acc[i][2]); v1.y = __float2bfloat16_rn(acc[i][3]);
            p[0] = v0; p[1] = v1;
            if (tx == 0) g0[n] = sqrtf(1.0f + rs[i]);
        }
    } else {
        __syncthreads();
        #pragma unroll
        for (int i = 0; i < 4; i++)
            #pragma unroll
            for (int j = 0; j < 4; j++)
                Ts[(tx * 4 + j) * 65 + ty * 4 + i] = acc[i][j];
        if (tx == 0)
            #pragma unroll
            for (int i = 0; i < 4; i++)
                st_time[ty * 4 + i] = sqrtf(1.0f + rs[i]);
        __syncthreads();

        __nv_bfloat16* gv = g_Vt + (size_t)bh * 72 * N_;
        for (int idx = tid; idx < 64 * 64; idx += 256) {
            int d = idx >> 6, n = idx & 63;
            gv[(size_t)(1 + d) * N_ + n0 + n] = __float2bfloat16_rn(Ts[d * 65 + n]);
        }
        if (tid < 64)
            gv[n0 + tid] = __float2bfloat16_rn(st_time[tid]);
        for (int idx = tid; idx < 7 * 64; idx += 256)
            gv[(size_t)(65 + (idx >> 6)) * N_ + n0 + (idx & 63)] = __float2bfloat16_rn(0.0f);
    }
}

// ---------------- mma.sync attention -----------------------------------------
// BM=128 q-rows/CTA, BN=64 keys/tile, 32 tiles. 8 warps, 16 rows/warp.
// SMEM: Q [128][72] bf16 | aq0 [128] f32 | 2 stages { K [64][72] bf16,
//       V [72][72] bf16, k0 [64] f32 }
#define OFF_Q    0
#define OFF_AQ0  18432
#define OFF_ST   18944
#define STG_V    9216
#define STG_K0   19584
#define STG_SZ   19840
#define ATTN_SMEM (OFF_ST + 2*STG_SZ)   // 58624

__global__ __launch_bounds__(256, 2) void attn_kernel(const float* __restrict__ scale_p)
{
    extern __shared__ char smem[];
    const uint32_t sb = smem_u32(smem);
    const int tid = threadIdx.x, wid = tid >> 5, lane = tid & 31;
    const int bh  = blockIdx.y;
    const int q0g = blockIdx.x * 128;

    const __nv_bfloat16* Qg = g_Qb + (size_t)bh * N_ * 64;
    const __nv_bfloat16* Kg = g_Kb + (size_t)bh * N_ * 64;
    const __nv_bfloat16* Vg = g_Vt + (size_t)bh * 72 * N_;
    const float* k0g = g_K0 + (size_t)bh * N_;

    const float a2c = 2.0f * 1.4426950408889634f / (scale_p[0] + EPS_);

    // prologue: Q + stage0 (group 0), stage1 (group 1)
    for (int i = tid; i < 1024; i += 256) {
        int r = i >> 3, c = i & 7;
        cpa16(sb + OFF_Q + r * 144 + c * 16, Qg + (size_t)(q0g + r) * 64 + c * 8);
    }
    for (int i = tid; i < 512; i += 256) {
        int r = i >> 3, c = i & 7;
        cpa16(sb + OFF_ST + r * 144 + c * 16, Kg + (size_t)r * 64 + c * 8);
    }
    for (int i = tid; i < 576; i += 256) {
        int a = i >> 3, c = i & 7;
        cpa16(sb + OFF_ST + STG_V + a * 144 + c * 16, Vg + (size_t)a * N_ + c * 8);
    }
    if (tid < 16) cpa16(sb + OFF_ST + STG_K0 + tid * 16, k0g + tid * 4);
    CP_COMMIT();
    for (int i = tid; i < 512; i += 256) {
        int r = i >> 3, c = i & 7;
        cpa16(sb + OFF_ST + STG_SZ + r * 144 + c * 16, Kg + (size_t)(64 + r) * 64 + c * 8);
    }
    for (int i = tid; i < 576; i += 256) {
        int a = i >> 3, c = i & 7;
        cpa16(sb + OFF_ST + STG_SZ + STG_V + a * 144 + c * 16, Vg + (size_t)a * N_ + 64 + c * 8);
    }
    if (tid < 16) cpa16(sb + OFF_ST + STG_SZ + STG_K0 + tid * 16, k0g + 64 + tid * 4);
    CP_COMMIT();

    if (tid < 128)
        ((float*)(smem + OFF_AQ0))[tid] = a2c * g_Q0[(size_t)bh * N_ + q0g + tid];
    __syncthreads();

    const int r0 = wid * 16;
    const int lq = lane >> 2;          // 0..7
    const int lm = lane & 3;           // 0..3
    const float aq00 = ((const float*)(smem + OFF_AQ0))[r0 + lq];
    const float aq01 = ((const float*)(smem + OFF_AQ0))[r0 + lq + 8];
    const uint32_t* QSw = (const uint32_t*)(smem + OFF_Q);

    float o[9][4];
    #pragma unroll
    for (int i = 0; i < 9; i++)
        #pragma unroll
        for (int j = 0; j < 4; j++) o[i][j] = 0.f;
    float lsum0 = 0.f, lsum1 = 0.f;

    for (int t = 0; t < 32; t++) {
        const uint32_t stg = OFF_ST + (t & 1) * STG_SZ;
        CP_WAIT1();
        __syncthreads();
        const uint32_t* KS  = (const uint32_t*)(smem + stg);
        const uint32_t* VS  = (const uint32_t*)(smem + stg + STG_V);
        const float*    k0s = (const float*)(smem + stg + STG_K0);

        // S = Q_spatial . K_spatial^T  (16 rows x 64 keys per warp)
        float s[8][4];
        #pragma unroll
        for (int i = 0; i < 8; i++)
            #pragma unroll
            for (int j = 0; j < 4; j++) s[i][j] = 0.f;

        #pragma unroll
        for (int ks = 0; ks < 4; ks++) {
            const int dw = ks * 8 + lm;
            uint32_t a0 = QSw[(r0 + lq) * 36 + dw];
            uint32_t a1 = QSw[(r0 + lq + 8) * 36 + dw];
            uint32_t a2 = QSw[(r0 + lq) * 36 + dw + 4];
            uint32_t a3 = QSw[(r0 + lq + 8) * 36 + dw + 4];
            #pragma unroll
            for (int jt = 0; jt < 8; jt++) {
                uint32_t b0 = KS[(jt * 8 + lq) * 36 + dw];
                uint32_t b1 = KS[(jt * 8 + lq) * 36 + dw + 4];
                mma16816(s[jt], a0, a1, a2, a3, b0, b1);
            }
        }

        // softmax: p = exp2(a2*dot - (a2*q0)*k0); pack to bf16 A-fragments
        uint32_t pf[8][2];
        #pragma unroll
        for (int jt = 0; jt < 8; jt++) {
            float k0a = k0s[jt * 8 + lm * 2];
            float k0b = k0s[jt * 8 + lm * 2 + 1];
            float p0 = ex2f(fmaf(a2c, s[jt][0], -aq00 * k0a));
            float p1 = ex2f(fmaf(a2c, s[jt][1], -aq00 * k0b));
            float p2 = ex2f(fmaf(a2c, s[jt][2], -aq01 * k0a));
            float p3 = ex2f(fmaf(a2c, s[jt][3], -aq01 * k0b));
            lsum0 += p0 + p1;
            lsum1 += p2 + p3;
            pf[jt][0] = bf2(p0, p1);
            pf[jt][1] = bf2(p2, p3);
        }

        // O += P . V   (V^T in smem: [a][j], b32 = two consecutive j)
        #pragma unroll
        for (int kt = 0; kt < 4; kt++) {
            uint32_t a0 = pf[2*kt][0],   a1 = pf[2*kt][1];
            uint32_t a2 = pf[2*kt+1][0], a3 = pf[2*kt+1][1];
            #pragma unroll
            for (int at = 0; at < 9; at++) {
                uint32_t b0 = VS[(at * 8 + lq) * 36 + kt * 8 + lm];
                uint32_t b1 = VS[(at * 8 + lq) * 36 + kt * 8 + lm + 4];
                mma16816(o[at], a0, a1, a2, a3, b0, b1);
            }
        }
        __syncthreads();

        if (t < 30) {
            const int j0 = (t + 2) * 64;
            for (int i = tid; i < 512; i += 256) {
                int r = i >> 3, c = i & 7;
                cpa16(sb + stg + r * 144 + c * 16, Kg + (size_t)(j0 + r) * 64 + c * 8);
            }
            for (int i = tid; i < 576; i += 256) {
                int a = i >> 3, c = i & 7;
                cpa16(sb + stg + STG_V + a * 144 + c * 16, Vg + (size_t)a * N_ + j0 + c * 8);
            }
            if (tid < 16) cpa16(sb + stg + STG_K0 + tid * 16, k0g + j0 + tid * 4);
        }
        CP_COMMIT();
    }

    // reduce row sums across the quad, normalize, write Mu
    lsum0 += __shfl_xor_sync(0xffffffffu, lsum0, 1);
    lsum0 += __shfl_xor_sync(0xffffffffu, lsum0, 2);
    lsum1 += __shfl_xor_sync(0xffffffffu, lsum1, 1);
    lsum1 += __shfl_xor_sync(0xffffffffu, lsum1, 2);
    const float inv0 = 1.0f / lsum0;
    const float inv1 = 1.0f / lsum1;

    float* mA = g_Mu + ((size_t)bh * N_ + q0g + r0 + lq) * MUP_;
    float* mB = mA + 8 * MUP_;
    #pragma unroll
    for (int at = 0; at < 9; at++) {
        int ac = at * 8 + lm * 2;
        if (ac < 65)     { mA[ac]     = o[at][0] * inv0; mB[ac]     = o[at][2] * inv1; }
        if (ac + 1 < 65) { mA[ac + 1] = o[at][1] * inv0; mB[ac + 1] = o[at][3] * inv1; }
    }
}

// ---------------- finalize ---------------------------------------------------
__global__ __launch_bounds__(256) void finalize_kernel(float* __restrict__ out)
{
    const int gw = (blockIdx.x * blockDim.x + threadIdx.x) >> 5;
    const int lane = threadIdx.x & 31;
    if (gw >= B_ * N_) return;
    const int b = gw >> 11, n = gw & (N_ - 1);

    float a0 = 0.f, a1 = 0.f, a2 = 0.f;
    for (int h = 0; h < H_; h++) {
        const float* mu = g_Mu + ((size_t)(b * H_ + h) * N_ + n) * MUP_;
        float m0 = mu[lane];
        float m1 = mu[lane + 32];
        float m2 = (lane == 0) ? mu[64] : 0.f;
        float ss = m0 * m0 + m1 * m1 + m2 * m2;
        #pragma unroll
        for (int o = 16; o; o >>= 1) ss += __shfl_xor_sync(0xffffffffu, ss, o);
        float mu0 = __shfl_sync(0xffffffffu, m0, 0);
        float neg = 2.0f * mu0 * mu0 - ss;
        float inv = rsqrtf(fmaxf(neg, EPS_)) * (1.0f / H_);
        a0 += m0 * inv; a1 += m1 * inv; a2 += m2 * inv;
    }
    float ss = a0 * a0 + a1 * a1 + a2 * a2;
    #pragma unroll
    for (int o = 16; o; o >>= 1) ss += __shfl_xor_sync(0xffffffffu, ss, o);
    float av0 = __shfl_sync(0xffffffffu, a0, 0);
    float neg = 2.0f * av0 * av0 - ss;
    float inv2 = rsqrtf(fmaxf(neg, EPS_));
    float sp0 = a0 * inv2, sp1 = a1 * inv2, sp2 = a2 * inv2;

    float ssp = sp1 * sp1 + ((lane == 0) ? sp2 * sp2 : sp0 * sp0);
    #pragma unroll
    for (int o = 16; o; o >>= 1) ssp += __shfl_xor_sync(0xffffffffu, ssp, o);
    float t = sqrtf(1.0f + ssp);

    float* o_ = out + ((size_t)b * N_ + n) * AD_;
    o_[lane]      = (lane == 0) ? t : sp0;
    o_[lane + 32] = sp1;
    if (lane == 0) o_[64] = sp2;
}

// ---------------- launch -----------------------------------------------------
extern "C" void kernel_launch(void* const* d_in, const int* in_sizes, int n_in,
                              void* d_out, int out_size)
{
    const float* x     = (const float*)d_in[0];
    const float* Wq    = (const float*)d_in[1];
    const float* Wk    = (const float*)d_in[2];
    const float* Wv    = (const float*)d_in[3];
    const float* bq    = (const float*)d_in[4];
    const float* bk    = (const float*)d_in[5];
    const float* bv    = (const float*)d_in[6];
    const float* scale = (const float*)d_in[7];
    float* out = (float*)d_out;

    cudaFuncSetAttribute(proj_kernel, cudaFuncAttributeMaxDynamicSharedMemorySize, PROJ_SMEM);
    cudaFuncSetAttribute(attn_kernel, cudaFuncAttributeMaxDynamicSharedMemorySize, ATTN_SMEM);

    proj_kernel<<<dim3(N_/64, 3*H_, B_), 256, PROJ_SMEM>>>(x, Wq, Wk, Wv, bq, bk, bv);
    attn_kernel<<<dim3(N_/128, BH_), 256, ATTN_SMEM>>>(scale);
    finalize_kernel<<<(B_*N_*32 + 255)/256, 256>>>(out);
}

// round 4
// speedup vs baseline: 6.5855x; 1.4575x over previous
#include <cuda_runtime.h>
#include <cuda_bf16.h>
#include <math.h>
#include <stdint.h>

#define B_   4
#define N_   2048
#define KD_  129
#define H_   8
#define DO_  64
#define AD_  65
#define BH_  (B_*H_)
#define EPS_ 1e-7f
#define MUP_ 68
#define KP_  144      // padded K for projection (9 x 16)

// ---------------- scratch ----------------------------------------------------
__device__ __nv_bfloat16 g_Xb[B_*N_*KP_];        // x padded bf16
__device__ __nv_bfloat16 g_Wb[24*DO_*KP_];       // W d-major [idx][d][k]
__device__ __nv_bfloat16 g_Qb[BH_*N_*64];
__device__ __nv_bfloat16 g_Kb[BH_*N_*64];
__device__ float         g_Q0[BH_*N_];
__device__ float         g_K0[BH_*N_];
__device__ __nv_bfloat16 g_Vt[BH_*72*N_];        // V^T [bh][72][N], row0=time
__device__ float         g_Mu[BH_*N_*MUP_];

// ---------------- helpers ----------------------------------------------------
__device__ __forceinline__ uint32_t smem_u32(const void* p) {
    uint32_t a;
    asm("{ .reg .u64 t; cvta.to.shared.u64 t, %1; cvt.u32.u64 %0, t; }" : "=r"(a) : "l"(p));
    return a;
}
__device__ __forceinline__ void cpa16(uint32_t dst, const void* src) {
    asm volatile("cp.async.cg.shared.global [%0], [%1], 16;" :: "r"(dst), "l"(src));
}
#define CP_COMMIT() asm volatile("cp.async.commit_group;" ::: "memory")
#define CP_WAIT1()  asm volatile("cp.async.wait_group 1;" ::: "memory")
#define CP_WAIT0()  asm volatile("cp.async.wait_group 0;" ::: "memory")

__device__ __forceinline__ void mma16816(float* d,
    uint32_t a0, uint32_t a1, uint32_t a2, uint32_t a3,
    uint32_t b0, uint32_t b1)
{
    asm volatile("mma.sync.aligned.m16n8k16.row.col.f32.bf16.bf16.f32 "
        "{%0,%1,%2,%3}, {%4,%5,%6,%7}, {%8,%9}, {%0,%1,%2,%3};"
        : "+f"(d[0]), "+f"(d[1]), "+f"(d[2]), "+f"(d[3])
        : "r"(a0), "r"(a1), "r"(a2), "r"(a3), "r"(b0), "r"(b1));
}
__device__ __forceinline__ float ex2f(float x) {
    float r; asm("ex2.approx.ftz.f32 %0, %1;" : "=f"(r) : "f"(x)); return r;
}
__device__ __forceinline__ uint32_t bf2(float lo, float hi) {
    uint32_t r; asm("cvt.rn.bf16x2.f32 %0, %1, %2;" : "=r"(r) : "f"(hi), "f"(lo)); return r;
}

// ---------------- prep: bf16 conversion + padding -----------------------------
__global__ __launch_bounds__(256) void prep_kernel(
    const float* __restrict__ x,
    const float* __restrict__ Wq, const float* __restrict__ Wk,
    const float* __restrict__ Wv)
{
    const int nt = gridDim.x * 256;
    const int t0 = blockIdx.x * 256 + threadIdx.x;

    // x -> g_Xb [B*N][144]
    for (int i = t0; i < B_*N_*KP_; i += nt) {
        int bn = i / KP_, c = i - bn * KP_;
        g_Xb[i] = __float2bfloat16_rn(c < KD_ ? x[(size_t)bn * KD_ + c] : 0.f);
    }
    // W -> g_Wb [idx=m*8+h][d][k]
    for (int i = t0; i < 24*DO_*KP_; i += nt) {
        int idx = i / (DO_*KP_);
        int r   = i - idx * (DO_*KP_);
        int d   = r / KP_, k = r - d * KP_;
        int m = idx >> 3, h = idx & 7;
        const float* W = (m == 0 ? Wq : (m == 1 ? Wk : Wv)) + h * KD_ * DO_;
        g_Wb[i] = __float2bfloat16_rn(k < KD_ ? W[k * DO_ + d] : 0.f);
    }
    // zero V^T pad rows 65..71
    for (int i = t0; i < BH_*7*N_; i += nt) {
        int bh = i / (7*N_);
        int r  = i - bh * (7*N_);
        g_Vt[(size_t)bh * 72 * N_ + (size_t)(65 + r / N_) * N_ + (r % N_)] =
            __float2bfloat16_rn(0.f);
    }
}

// ---------------- projection via mma.sync -------------------------------------
// CTA: 128 rows x 64 cols, K=144. 8 warps x 16 rows.
#define PX_ST 76                       // b32 words per X row in smem
#define PROJ_XS_B (128*PX_ST*4)        // 38912
#define PROJ_WS_B (64*PX_ST*4)         // 19456
#define PROJ_SMEM (PROJ_XS_B + PROJ_WS_B)
#define TS_ST 136                      // bf16 stride for V staging overlay

__global__ __launch_bounds__(256, 2) void proj_kernel(
    const float* __restrict__ bq, const float* __restrict__ bk,
    const float* __restrict__ bv)
{
    extern __shared__ char smem[];
    const uint32_t sb = smem_u32(smem);
    const int tid = threadIdx.x, wid = tid >> 5, lane = tid & 31;
    const int n0 = blockIdx.x * 128;
    const int h  = blockIdx.y & 7;
    const int m  = blockIdx.y >> 3;
    const int b  = blockIdx.z;
    const int bh = b * H_ + h;
    const int widx = blockIdx.y;

    const __nv_bfloat16* Xg = g_Xb + (size_t)b * N_ * KP_;
    const __nv_bfloat16* Wg = g_Wb + (size_t)widx * DO_ * KP_;
    const float* bias = (m == 0 ? bq : (m == 1 ? bk : bv)) + h * DO_;

    // load X tile (128 rows x 288B) and W tile (64 rows x 288B)
    for (int i = tid; i < 128 * 18; i += 256) {
        int r = i / 18, c = i - r * 18;
        cpa16(sb + r * (PX_ST*4) + c * 16, Xg + (size_t)(n0 + r) * KP_ + c * 8);
    }
    for (int i = tid; i < 64 * 18; i += 256) {
        int r = i / 18, c = i - r * 18;
        cpa16(sb + PROJ_XS_B + r * (PX_ST*4) + c * 16, Wg + (size_t)r * KP_ + c * 8);
    }
    CP_COMMIT();
    CP_WAIT0();
    __syncthreads();

    const int r0 = wid * 16;
    const int lq = lane >> 2, lm = lane & 3;
    const uint32_t* XS = (const uint32_t*)smem;
    const uint32_t* WS = (const uint32_t*)(smem + PROJ_XS_B);

    float o[8][4];
    #pragma unroll
    for (int jt = 0; jt < 8; jt++) {
        float b0v = bias[jt * 8 + 2 * lm];
        float b1v = bias[jt * 8 + 2 * lm + 1];
        o[jt][0] = b0v; o[jt][1] = b1v; o[jt][2] = b0v; o[jt][3] = b1v;
    }

    #pragma unroll
    for (int ks = 0; ks < 9; ks++) {
        const int dw = ks * 8 + lm;
        uint32_t a0 = XS[(r0 + lq) * PX_ST + dw];
        uint32_t a1 = XS[(r0 + lq + 8) * PX_ST + dw];
        uint32_t a2 = XS[(r0 + lq) * PX_ST + dw + 4];
        uint32_t a3 = XS[(r0 + lq + 8) * PX_ST + dw + 4];
        #pragma unroll
        for (int jt = 0; jt < 8; jt++) {
            uint32_t b0 = WS[(jt * 8 + lq) * PX_ST + dw];
            uint32_t b1 = WS[(jt * 8 + lq) * PX_ST + dw + 4];
            mma16816(o[jt], a0, a1, a2, a3, b0, b1);
        }
    }

    // row sums of squares -> lift times
    float rs0 = 0.f, rs1 = 0.f;
    #pragma unroll
    for (int jt = 0; jt < 8; jt++) {
        rs0 += o[jt][0]*o[jt][0] + o[jt][1]*o[jt][1];
        rs1 += o[jt][2]*o[jt][2] + o[jt][3]*o[jt][3];
    }
    rs0 += __shfl_xor_sync(0xffffffffu, rs0, 1);
    rs0 += __shfl_xor_sync(0xffffffffu, rs0, 2);
    rs1 += __shfl_xor_sync(0xffffffffu, rs1, 1);
    rs1 += __shfl_xor_sync(0xffffffffu, rs1, 2);
    const float t0v = sqrtf(1.0f + rs0);
    const float t1v = sqrtf(1.0f + rs1);

    const int nA = n0 + r0 + lq, nB = nA + 8;

    if (m < 2) {
        __nv_bfloat16* gb = (m == 0 ? g_Qb : g_Kb) + (size_t)bh * N_ * 64;
        float*         g0 = (m == 0 ? g_Q0 : g_K0) + (size_t)bh * N_;
        #pragma unroll
        for (int jt = 0; jt < 8; jt++) {
            *(uint32_t*)(gb + (size_t)nA * 64 + jt * 8 + 2 * lm) = bf2(o[jt][0], o[jt][1]);
            *(uint32_t*)(gb + (size_t)nB * 64 + jt * 8 + 2 * lm) = bf2(o[jt][2], o[jt][3]);
        }
        if (lm == 0) { g0[nA] = t0v; g0[nB] = t1v; }
    } else {
        __syncthreads();   // WS dead -> Ts overlay
        __nv_bfloat16* Ts = (__nv_bfloat16*)(smem + PROJ_XS_B);
        const int rA = r0 + lq, rB = rA + 8;
        #pragma unroll
        for (int jt = 0; jt < 8; jt++) {
            int c0 = jt * 8 + 2 * lm;
            Ts[(c0 + 1) * TS_ST + rA] = __float2bfloat16_rn(o[jt][0]);
            Ts[(c0 + 2) * TS_ST + rA] = __float2bfloat16_rn(o[jt][1]);
            Ts[(c0 + 1) * TS_ST + rB] = __float2bfloat16_rn(o[jt][2]);
            Ts[(c0 + 2) * TS_ST + rB] = __float2bfloat16_rn(o[jt][3]);
        }
        if (lm == 0) { Ts[rA] = __float2bfloat16_rn(t0v); Ts[rB] = __float2bfloat16_rn(t1v); }
        __syncthreads();

        __nv_bfloat16* gv = g_Vt + (size_t)bh * 72 * N_;
        for (int i = tid; i < 65 * 16; i += 256) {
            int a = i >> 4, ch = i & 15;
            uint4 v = *(const uint4*)(Ts + a * TS_ST + ch * 8);
            *(uint4*)(gv + (size_t)a * N_ + n0 + ch * 8) = v;
        }
    }
}

// ---------------- mma.sync attention (unchanged from round 3) -----------------
#define OFF_Q    0
#define OFF_AQ0  18432
#define OFF_ST   18944
#define STG_V    9216
#define STG_K0   19584
#define STG_SZ   19840
#define ATTN_SMEM (OFF_ST + 2*STG_SZ)

__global__ __launch_bounds__(256, 2) void attn_kernel(const float* __restrict__ scale_p)
{
    extern __shared__ char smem[];
    const uint32_t sb = smem_u32(smem);
    const int tid = threadIdx.x, wid = tid >> 5, lane = tid & 31;
    const int bh  = blockIdx.y;
    const int q0g = blockIdx.x * 128;

    const __nv_bfloat16* Qg = g_Qb + (size_t)bh * N_ * 64;
    const __nv_bfloat16* Kg = g_Kb + (size_t)bh * N_ * 64;
    const __nv_bfloat16* Vg = g_Vt + (size_t)bh * 72 * N_;
    const float* k0g = g_K0 + (size_t)bh * N_;

    const float a2c = 2.0f * 1.4426950408889634f / (scale_p[0] + EPS_);

    for (int i = tid; i < 1024; i += 256) {
        int r = i >> 3, c = i & 7;
        cpa16(sb + OFF_Q + r * 144 + c * 16, Qg + (size_t)(q0g + r) * 64 + c * 8);
    }
    for (int i = tid; i < 512; i += 256) {
        int r = i >> 3, c = i & 7;
        cpa16(sb + OFF_ST + r * 144 + c * 16, Kg + (size_t)r * 64 + c * 8);
    }
    for (int i = tid; i < 576; i += 256) {
        int a = i >> 3, c = i & 7;
        cpa16(sb + OFF_ST + STG_V + a * 144 + c * 16, Vg + (size_t)a * N_ + c * 8);
    }
    if (tid < 16) cpa16(sb + OFF_ST + STG_K0 + tid * 16, k0g + tid * 4);
    CP_COMMIT();
    for (int i = tid; i < 512; i += 256) {
        int r = i >> 3, c = i & 7;
        cpa16(sb + OFF_ST + STG_SZ + r * 144 + c * 16, Kg + (size_t)(64 + r) * 64 + c * 8);
    }
    for (int i = tid; i < 576; i += 256) {
        int a = i >> 3, c = i & 7;
        cpa16(sb + OFF_ST + STG_SZ + STG_V + a * 144 + c * 16, Vg + (size_t)a * N_ + 64 + c * 8);
    }
    if (tid < 16) cpa16(sb + OFF_ST + STG_SZ + STG_K0 + tid * 16, k0g + 64 + tid * 4);
    CP_COMMIT();

    if (tid < 128)
        ((float*)(smem + OFF_AQ0))[tid] = a2c * g_Q0[(size_t)bh * N_ + q0g + tid];
    __syncthreads();

    const int r0 = wid * 16;
    const int lq = lane >> 2;
    const int lm = lane & 3;
    const float aq00 = ((const float*)(smem + OFF_AQ0))[r0 + lq];
    const float aq01 = ((const float*)(smem + OFF_AQ0))[r0 + lq + 8];
    const uint32_t* QSw = (const uint32_t*)(smem + OFF_Q);

    float o[9][4];
    #pragma unroll
    for (int i = 0; i < 9; i++)
        #pragma unroll
        for (int j = 0; j < 4; j++) o[i][j] = 0.f;
    float lsum0 = 0.f, lsum1 = 0.f;

    for (int t = 0; t < 32; t++) {
        const uint32_t stg = OFF_ST + (t & 1) * STG_SZ;
        CP_WAIT1();
        __syncthreads();
        const uint32_t* KS  = (const uint32_t*)(smem + stg);
        const uint32_t* VS  = (const uint32_t*)(smem + stg + STG_V);
        const float*    k0s = (const float*)(smem + stg + STG_K0);

        float s[8][4];
        #pragma unroll
        for (int i = 0; i < 8; i++)
            #pragma unroll
            for (int j = 0; j < 4; j++) s[i][j] = 0.f;

        #pragma unroll
        for (int ks = 0; ks < 4; ks++) {
            const int dw = ks * 8 + lm;
            uint32_t a0 = QSw[(r0 + lq) * 36 + dw];
            uint32_t a1 = QSw[(r0 + lq + 8) * 36 + dw];
            uint32_t a2 = QSw[(r0 + lq) * 36 + dw + 4];
            uint32_t a3 = QSw[(r0 + lq + 8) * 36 + dw + 4];
            #pragma unroll
            for (int jt = 0; jt < 8; jt++) {
                uint32_t b0 = KS[(jt * 8 + lq) * 36 + dw];
                uint32_t b1 = KS[(jt * 8 + lq) * 36 + dw + 4];
                mma16816(s[jt], a0, a1, a2, a3, b0, b1);
            }
        }

        uint32_t pf[8][2];
        #pragma unroll
        for (int jt = 0; jt < 8; jt++) {
            float k0a = k0s[jt * 8 + lm * 2];
            float k0b = k0s[jt * 8 + lm * 2 + 1];
            float p0 = ex2f(fmaf(a2c, s[jt][0], -aq00 * k0a));
            float p1 = ex2f(fmaf(a2c, s[jt][1], -aq00 * k0b));
            float p2 = ex2f(fmaf(a2c, s[jt][2], -aq01 * k0a));
            float p3 = ex2f(fmaf(a2c, s[jt][3], -aq01 * k0b));
            lsum0 += p0 + p1;
            lsum1 += p2 + p3;
            pf[jt][0] = bf2(p0, p1);
            pf[jt][1] = bf2(p2, p3);
        }

        #pragma unroll
        for (int kt = 0; kt < 4; kt++) {
            uint32_t a0 = pf[2*kt][0],   a1 = pf[2*kt][1];
            uint32_t a2 = pf[2*kt+1][0], a3 = pf[2*kt+1][1];
            #pragma unroll
            for (int at = 0; at < 9; at++) {
                uint32_t b0 = VS[(at * 8 + lq) * 36 + kt * 8 + lm];
                uint32_t b1 = VS[(at * 8 + lq) * 36 + kt * 8 + lm + 4];
                mma16816(o[at], a0, a1, a2, a3, b0, b1);
            }
        }
        __syncthreads();

        if (t < 30) {
            const int j0 = (t + 2) * 64;
            for (int i = tid; i < 512; i += 256) {
                int r = i >> 3, c = i & 7;
                cpa16(sb + stg + r * 144 + c * 16, Kg + (size_t)(j0 + r) * 64 + c * 8);
            }
            for (int i = tid; i < 576; i += 256) {
                int a = i >> 3, c = i & 7;
                cpa16(sb + stg + STG_V + a * 144 + c * 16, Vg + (size_t)a * N_ + j0 + c * 8);
            }
            if (tid < 16) cpa16(sb + stg + STG_K0 + tid * 16, k0g + j0 + tid * 4);
        }
        CP_COMMIT();
    }

    lsum0 += __shfl_xor_sync(0xffffffffu, lsum0, 1);
    lsum0 += __shfl_xor_sync(0xffffffffu, lsum0, 2);
    lsum1 += __shfl_xor_sync(0xffffffffu, lsum1, 1);
    lsum1 += __shfl_xor_sync(0xffffffffu, lsum1, 2);
    const float inv0 = 1.0f / lsum0;
    const float inv1 = 1.0f / lsum1;

    float* mA = g_Mu + ((size_t)bh * N_ + q0g + r0 + lq) * MUP_;
    float* mB = mA + 8 * MUP_;
    #pragma unroll
    for (int at = 0; at < 9; at++) {
        int ac = at * 8 + lm * 2;
        if (ac < 65)     { mA[ac]     = o[at][0] * inv0; mB[ac]     = o[at][2] * inv1; }
        if (ac + 1 < 65) { mA[ac + 1] = o[at][1] * inv0; mB[ac + 1] = o[at][3] * inv1; }
    }
}

// ---------------- finalize ----------------------------------------------------
__global__ __launch_bounds__(256) void finalize_kernel(float* __restrict__ out)
{
    const int gw = (blockIdx.x * blockDim.x + threadIdx.x) >> 5;
    const int lane = threadIdx.x & 31;
    if (gw >= B_ * N_) return;
    const int b = gw >> 11, n = gw & (N_ - 1);

    float a0 = 0.f, a1 = 0.f, a2 = 0.f;
    for (int h = 0; h < H_; h++) {
        const float* mu = g_Mu + ((size_t)(b * H_ + h) * N_ + n) * MUP_;
        float m0 = mu[lane];
        float m1 = mu[lane + 32];
        float m2 = (lane == 0) ? mu[64] : 0.f;
        float ss = m0 * m0 + m1 * m1 + m2 * m2;
        #pragma unroll
        for (int o = 16; o; o >>= 1) ss += __shfl_xor_sync(0xffffffffu, ss, o);
        float mu0 = __shfl_sync(0xffffffffu, m0, 0);
        float neg = 2.0f * mu0 * mu0 - ss;
        float inv = rsqrtf(fmaxf(neg, EPS_)) * (1.0f / H_);
        a0 += m0 * inv; a1 += m1 * inv; a2 += m2 * inv;
    }
    float ss = a0 * a0 + a1 * a1 + a2 * a2;
    #pragma unroll
    for (int o = 16; o; o >>= 1) ss += __shfl_xor_sync(0xffffffffu, ss, o);
    float av0 = __shfl_sync(0xffffffffu, a0, 0);
    float neg = 2.0f * av0 * av0 - ss;
    float inv2 = rsqrtf(fmaxf(neg, EPS_));
    float sp0 = a0 * inv2, sp1 = a1 * inv2, sp2 = a2 * inv2;

    float ssp = sp1 * sp1 + ((lane == 0) ? sp2 * sp2 : sp0 * sp0);
    #pragma unroll
    for (int o = 16; o; o >>= 1) ssp += __shfl_xor_sync(0xffffffffu, ssp, o);
    float t = sqrtf(1.0f + ssp);

    float* o_ = out + ((size_t)b * N_ + n) * AD_;
    o_[lane]      = (lane == 0) ? t : sp0;
    o_[lane + 32] = sp1;
    if (lane == 0) o_[64] = sp2;
}

// ---------------- launch ------------------------------------------------------
extern "C" void kernel_launch(void* const* d_in, const int* in_sizes, int n_in,
                              void* d_out, int out_size)
{
    const float* x     = (const float*)d_in[0];
    const float* Wq    = (const float*)d_in[1];
    const float* Wk    = (const float*)d_in[2];
    const float* Wv    = (const float*)d_in[3];
    const float* bq    = (const float*)d_in[4];
    const float* bk    = (const float*)d_in[5];
    const float* bv    = (const float*)d_in[6];
    const float* scale = (const float*)d_in[7];
    float* out = (float*)d_out;

    cudaFuncSetAttribute(proj_kernel, cudaFuncAttributeMaxDynamicSharedMemorySize, PROJ_SMEM);
    cudaFuncSetAttribute(attn_kernel, cudaFuncAttributeMaxDynamicSharedMemorySize, ATTN_SMEM);

    prep_kernel<<<1024, 256>>>(x, Wq, Wk, Wv);
    proj_kernel<<<dim3(N_/128, 24, B_), 256, PROJ_SMEM>>>(bq, bk, bv);
    attn_kernel<<<dim3(N_/128, BH_), 256, ATTN_SMEM>>>(scale);
    finalize_kernel<<<(B_*N_*32 + 255)/256, 256>>>(out);
}